// round 14
// baseline (speedup 1.0000x reference)
#include <cuda_runtime.h>
#include <cstddef>

// Problem constants (fixed shapes from reference setup_inputs)
#define T_STEPS 16
#define B_SZ    512
#define F_IN    2048
#define H_SZ    2048
#define OUT_SZ  1024
#define BT      (B_SZ * T_STEPS)   // 8192

// Scratch (device globals: allocation-free per harness rules)
__device__ float g_H  [ (size_t)BT  * H_SZ   ];   // 64 MB: fc1 pre-activations, all t
__device__ float g_v1 [ (size_t)B_SZ * H_SZ  ];   // membrane lif1
__device__ float g_v2 [ (size_t)B_SZ * OUT_SZ];   // membrane lif_out
__device__ float g_W2T[ (size_t)H_SZ * OUT_SZ];   // 8 MB: W2 transposed [H, OUT]

// ---------------------------------------------------------------------------
// init: zero membranes
// ---------------------------------------------------------------------------
__global__ void init_state_kernel() {
    size_t i = (size_t)blockIdx.x * blockDim.x + threadIdx.x;
    size_t n1 = (size_t)B_SZ * H_SZ;
    size_t n2 = (size_t)B_SZ * OUT_SZ;
    if (i < n1) g_v1[i] = 0.0f;
    if (i < n2) g_v2[i] = 0.0f;
}

// ---------------------------------------------------------------------------
// Transpose W2 [OUT, H] -> W2T [H, OUT].  32x32 smem tiles.
// ---------------------------------------------------------------------------
__global__ void transpose_w2_kernel(const float* __restrict__ W2)
{
    __shared__ float tile[32][33];
    int o0 = blockIdx.y * 32;
    int k0 = blockIdx.x * 32;
    int tx = threadIdx.x, ty = threadIdx.y;   // 32 x 8

    #pragma unroll
    for (int r = 0; r < 32; r += 8)
        tile[ty + r][tx] = W2[(size_t)(o0 + ty + r) * H_SZ + k0 + tx];
    __syncthreads();
    #pragma unroll
    for (int r = 0; r < 32; r += 8)
        g_W2T[(size_t)(k0 + ty + r) * OUT_SZ + o0 + tx] = tile[tx][ty + r];
}

// ---------------------------------------------------------------------------
// GEMM1 phase kernel (H = x @ W1^T, one kc=1024 chunk per launch).
// ACCUMULATION CONTRACT (frozen, R6): per element, 2 contiguous chunks of
// 1024, each a serial ascending FMA chain from zero, merged sequentially.
//   Phase A (ACCUM=false): C  = chain(K[0:1024])
//   Phase B (ACCUM=true):  C  = __fadd_rn(C, chain(K[1024:2048]))
// R14: BK 16->32 — halves sync convergence points (the post-sync lockstep
// LDS stall was the residual issue-idle in R13) and halves staging bursts.
// Two-wave staging: A-wave (4 float4) loaded at tile start / stored mid,
// B-wave reuses the same regs, loaded mid / stored at end. Dynamic smem
// 64KB/CTA, 2 CTAs/SM. Fragment mapping (R13 strided) unchanged.
// Bitwise-safe: k ascending within tile, tiles ascending, phase merge same.
// ---------------------------------------------------------------------------
#define G1_BM 128
#define G1_BN 128
#define G1_BK 32
#define G1_KC 1024
#define G1_NT (G1_KC / G1_BK)        // 32 tiles per phase
#define G1_SMEM (2 * G1_BK * (G1_BM + G1_BN) * 4)   // 65536 bytes

template<bool ACCUM>
__global__ __launch_bounds__(256, 2)
void gemm1_phase_kernel(const float* __restrict__ A,    // x   [BT, F_IN]
                        const float* __restrict__ Bm,   // W1  [H, F_IN]
                        float* __restrict__ C,          // g_H [BT, H]
                        int k_base)
{
    extern __shared__ float smem[];
    float (*As)[G1_BK][G1_BM] = reinterpret_cast<float(*)[G1_BK][G1_BM]>(smem);
    float (*Bs)[G1_BK][G1_BN] =
        reinterpret_cast<float(*)[G1_BK][G1_BN]>(smem + 2 * G1_BK * G1_BM);

    const int tid = threadIdx.x;
    const int m0  = blockIdx.y * G1_BM;
    const int n0  = blockIdx.x * G1_BN;

    // Strided-fragment mapping (R13): warp 8x4, CTA warps 2x4.
    const int lane = tid & 31;
    const int warp = tid >> 5;
    const int ly   = lane >> 2;          // 0..7
    const int lx   = lane & 3;           // 0..3
    const int wy   = warp >> 2;          // 0..1
    const int wx   = warp & 3;           // 0..3
    const int rr   = (wy * 8 + ly) * 4;  // row base
    const int cc   = (wx * 4 + lx) * 4;  // col base

    // Staging map: per matrix 128x32 floats = 1024 float4; 4 items/thread.
    // item i = tid + 256*w: row = i>>3 (0..127), vec-col = i&7 (0..7).
    int   srow[4], scol[4];
    int   offA[4], offB[4];
    #pragma unroll
    for (int w = 0; w < 4; w++) {
        int item = tid + 256 * w;
        srow[w] = item >> 3;
        scol[w] = item & 7;
        offA[w] = (m0 + srow[w]) * F_IN + k_base + scol[w] * 4;
        offB[w] = (n0 + srow[w]) * F_IN + k_base + scol[w] * 4;
    }

    float acc[8][8];
    #pragma unroll
    for (int i = 0; i < 8; i++)
        #pragma unroll
        for (int j = 0; j < 8; j++)
            acc[i][j] = 0.0f;

    float4 st[4];

    // Prologue: tile 0 -> buffer 0 (A wave then B wave, reusing st[])
    #pragma unroll
    for (int w = 0; w < 4; w++)
        st[w] = *reinterpret_cast<const float4*>(A + offA[w]);
    #pragma unroll
    for (int w = 0; w < 4; w++) {
        As[0][scol[w]*4+0][srow[w]] = st[w].x;
        As[0][scol[w]*4+1][srow[w]] = st[w].y;
        As[0][scol[w]*4+2][srow[w]] = st[w].z;
        As[0][scol[w]*4+3][srow[w]] = st[w].w;
    }
    #pragma unroll
    for (int w = 0; w < 4; w++)
        st[w] = *reinterpret_cast<const float4*>(Bm + offB[w]);
    #pragma unroll
    for (int w = 0; w < 4; w++) {
        Bs[0][scol[w]*4+0][srow[w]] = st[w].x;
        Bs[0][scol[w]*4+1][srow[w]] = st[w].y;
        Bs[0][scol[w]*4+2][srow[w]] = st[w].z;
        Bs[0][scol[w]*4+3][srow[w]] = st[w].w;
    }
    __syncthreads();

    for (int kt = 0; kt < G1_NT; kt++) {
        const int buf  = kt & 1;
        const int nb   = 1 - buf;
        const int koff = (kt + 1) * G1_BK;
        const bool more = (kt + 1 < G1_NT);

        // Issue next A-wave loads (land during first half of compute)
        if (more) {
            #pragma unroll
            for (int w = 0; w < 4; w++)
                st[w] = *reinterpret_cast<const float4*>(A + offA[w] + koff);
        }

        // Compute k = 0..15 (serial ascending — frozen chain order)
        #pragma unroll
        for (int k = 0; k < 16; k++) {
            float4 a_lo = *reinterpret_cast<const float4*>(&As[buf][k][rr]);
            float4 a_hi = *reinterpret_cast<const float4*>(&As[buf][k][rr + 64]);
            float4 b_lo = *reinterpret_cast<const float4*>(&Bs[buf][k][cc]);
            float4 b_hi = *reinterpret_cast<const float4*>(&Bs[buf][k][cc + 64]);
            float a[8] = {a_lo.x, a_lo.y, a_lo.z, a_lo.w,
                          a_hi.x, a_hi.y, a_hi.z, a_hi.w};
            float b[8] = {b_lo.x, b_lo.y, b_lo.z, b_lo.w,
                          b_hi.x, b_hi.y, b_hi.z, b_hi.w};
            #pragma unroll
            for (int i = 0; i < 8; i++)
                #pragma unroll
                for (int j = 0; j < 8; j++)
                    acc[i][j] = fmaf(a[i], b[j], acc[i][j]);
        }

        // Store A-wave to next buffer; issue next B-wave loads (reuse regs)
        if (more) {
            #pragma unroll
            for (int w = 0; w < 4; w++) {
                As[nb][scol[w]*4+0][srow[w]] = st[w].x;
                As[nb][scol[w]*4+1][srow[w]] = st[w].y;
                As[nb][scol[w]*4+2][srow[w]] = st[w].z;
                As[nb][scol[w]*4+3][srow[w]] = st[w].w;
            }
            #pragma unroll
            for (int w = 0; w < 4; w++)
                st[w] = *reinterpret_cast<const float4*>(Bm + offB[w] + koff);
        }

        // Compute k = 16..31
        #pragma unroll
        for (int k = 16; k < 32; k++) {
            float4 a_lo = *reinterpret_cast<const float4*>(&As[buf][k][rr]);
            float4 a_hi = *reinterpret_cast<const float4*>(&As[buf][k][rr + 64]);
            float4 b_lo = *reinterpret_cast<const float4*>(&Bs[buf][k][cc]);
            float4 b_hi = *reinterpret_cast<const float4*>(&Bs[buf][k][cc + 64]);
            float a[8] = {a_lo.x, a_lo.y, a_lo.z, a_lo.w,
                          a_hi.x, a_hi.y, a_hi.z, a_hi.w};
            float b[8] = {b_lo.x, b_lo.y, b_lo.z, b_lo.w,
                          b_hi.x, b_hi.y, b_hi.z, b_hi.w};
            #pragma unroll
            for (int i = 0; i < 8; i++)
                #pragma unroll
                for (int j = 0; j < 8; j++)
                    acc[i][j] = fmaf(a[i], b[j], acc[i][j]);
        }

        // Store B-wave to next buffer
        if (more) {
            #pragma unroll
            for (int w = 0; w < 4; w++) {
                Bs[nb][scol[w]*4+0][srow[w]] = st[w].x;
                Bs[nb][scol[w]*4+1][srow[w]] = st[w].y;
                Bs[nb][scol[w]*4+2][srow[w]] = st[w].z;
                Bs[nb][scol[w]*4+3][srow[w]] = st[w].w;
            }
        }
        __syncthreads();
    }

    // Epilogue: rows {rr+i, rr+64+i}, cols {cc..cc+3, cc+64..cc+67}
    #pragma unroll
    for (int i = 0; i < 8; i++) {
        const int row = m0 + ((i < 4) ? (rr + i) : (rr + 64 + i - 4));
        #pragma unroll
        for (int jh = 0; jh < 2; jh++) {
            const int col = n0 + cc + jh * 64;
            float* cp = C + (size_t)row * H_SZ + col;
            const int j0 = jh * 4;
            if (ACCUM) {
                float4 prev = *reinterpret_cast<const float4*>(cp);
                float4 v = make_float4(__fadd_rn(prev.x, acc[i][j0+0]),
                                       __fadd_rn(prev.y, acc[i][j0+1]),
                                       __fadd_rn(prev.z, acc[i][j0+2]),
                                       __fadd_rn(prev.w, acc[i][j0+3]));
                *reinterpret_cast<float4*>(cp) = v;
            } else {
                float4 v = make_float4(acc[i][j0+0], acc[i][j0+1],
                                       acc[i][j0+2], acc[i][j0+3]);
                *reinterpret_cast<float4*>(cp) = v;
            }
        }
    }
}

// ---------------------------------------------------------------------------
// Fused timestep kernel: LIF1 + ordered compaction (smem) + sparse GEMM2 +
// LIF2. One CTA (256 threads) per batch row b. All accumulation orders
// identical to R8-R13 (bitwise contract).
// ---------------------------------------------------------------------------
__global__ __launch_bounds__(256)
void step_kernel(int t, float* __restrict__ out_ch, float* __restrict__ out_com)
{
    __shared__ int sk[H_SZ];    // spike k-indices, ascending (8 KB)
    __shared__ int sc[256];     // scan workspace

    const int b   = blockIdx.x;
    const int tid = threadIdx.x;
    const int PER = H_SZ / 256;   // 8

    const size_t hbase = ((size_t)b * T_STEPS + t) * H_SZ + (size_t)tid * PER;
    const size_t vbase = (size_t)b * H_SZ + (size_t)tid * PER;

    float h[PER], v[PER];
    #pragma unroll
    for (int j = 0; j < PER; j += 4) {
        float4 hv = *reinterpret_cast<const float4*>(&g_H[hbase + j]);
        h[j] = hv.x; h[j+1] = hv.y; h[j+2] = hv.z; h[j+3] = hv.w;
        float4 vv = *reinterpret_cast<const float4*>(&g_v1[vbase + j]);
        v[j] = vv.x; v[j+1] = vv.y; v[j+2] = vv.z; v[j+3] = vv.w;
    }

    float s[PER];
    int cnt = 0;
    #pragma unroll
    for (int j = 0; j < PER; j++) {
        float nv = __fmul_rn(__fadd_rn(v[j], h[j]), 0.5f);   // single rounding
        s[j] = (nv >= 0.5f) ? 1.0f : 0.0f;
        v[j] = (s[j] != 0.0f) ? 0.0f : nv;
        cnt += (s[j] != 0.0f) ? 1 : 0;
    }

    #pragma unroll
    for (int j = 0; j < PER; j += 4) {
        *reinterpret_cast<float4*>(&out_ch[hbase + j]) =
            make_float4(s[j], s[j+1], s[j+2], s[j+3]);
        *reinterpret_cast<float4*>(&g_v1[vbase + j]) =
            make_float4(v[j], v[j+1], v[j+2], v[j+3]);
    }

    // block inclusive scan of counts
    sc[tid] = cnt;
    __syncthreads();
    #pragma unroll
    for (int off = 1; off < 256; off <<= 1) {
        int add = (tid >= off) ? sc[tid - off] : 0;
        __syncthreads();
        sc[tid] += add;
        __syncthreads();
    }
    int pos = sc[tid] - cnt;   // exclusive prefix

    #pragma unroll
    for (int j = 0; j < PER; j++)
        if (s[j] != 0.0f)
            sk[pos++] = tid * PER + j;

    const int total = sc[255];
    __syncthreads();   // sk fully written before reads

    // sparse GEMM2: ascending-k sum == dense serial FMA chain (bitwise)
    const int o = tid * 4;
    float a0 = 0.0f, a1 = 0.0f, a2 = 0.0f, a3 = 0.0f;

    #pragma unroll 4
    for (int i = 0; i < total; i++) {
        const int k = sk[i];
        float4 w = *reinterpret_cast<const float4*>(&g_W2T[(size_t)k * OUT_SZ + o]);
        a0 = __fadd_rn(a0, w.x);
        a1 = __fadd_rn(a1, w.y);
        a2 = __fadd_rn(a2, w.z);
        a3 = __fadd_rn(a3, w.w);
    }

    // LIF2 epilogue
    const size_t v2base = (size_t)b * OUT_SZ + o;
    float4 vv = *reinterpret_cast<const float4*>(&g_v2[v2base]);
    float acc[4] = {a0, a1, a2, a3};
    float vin[4] = {vv.x, vv.y, vv.z, vv.w};
    float sp[4], vout[4];
    #pragma unroll
    for (int j = 0; j < 4; j++) {
        float nv = __fmul_rn(__fadd_rn(vin[j], acc[j]), 0.5f);
        sp[j]   = (nv >= 0.5f) ? 1.0f : 0.0f;
        vout[j] = (sp[j] != 0.0f) ? 0.0f : nv;
    }
    *reinterpret_cast<float4*>(
        &out_com[((size_t)b * T_STEPS + t) * OUT_SZ + o]) =
        make_float4(sp[0], sp[1], sp[2], sp[3]);
    *reinterpret_cast<float4*>(&g_v2[v2base]) =
        make_float4(vout[0], vout[1], vout[2], vout[3]);
}

// ---------------------------------------------------------------------------
// kernel_launch: graph-capturable, allocation-free.
// Inputs: d_in[0]=x [B,T,F_IN] f32, d_in[1]=W1 [H,F_IN] f32, d_in[2]=W2 [OUT,H] f32
// Output: concat(com_spk [B,T,OUT], ch_spk [B,T,H], x [B,T,F_IN]) f32
// ---------------------------------------------------------------------------
extern "C" void kernel_launch(void* const* d_in, const int* in_sizes, int n_in,
                              void* d_out, int out_size)
{
    const float* x  = (const float*)d_in[0];
    const float* W1 = (const float*)d_in[1];
    const float* W2 = (const float*)d_in[2];
    float* out = (float*)d_out;

    const size_t COM_OFF = 0;
    const size_t CH_OFF  = (size_t)BT * OUT_SZ;
    const size_t X_OFF   = CH_OFF + (size_t)BT * H_SZ;

    float* out_com = out + COM_OFF;
    float* out_ch  = out + CH_OFF;
    float* out_x   = out + X_OFF;

    // 0) zero membranes + transpose W2
    {
        size_t n = (size_t)B_SZ * H_SZ;
        init_state_kernel<<<(unsigned)((n + 255) / 256), 256>>>();
        dim3 tgrid(H_SZ / 32, OUT_SZ / 32);
        transpose_w2_kernel<<<tgrid, dim3(32, 8)>>>(W2);
    }

    // 1) H = x @ W1^T — two kc=1024 phases (frozen accumulation order)
    {
        float* g_H_p;
        cudaGetSymbolAddress((void**)&g_H_p, g_H);
        cudaFuncSetAttribute(gemm1_phase_kernel<false>,
                             cudaFuncAttributeMaxDynamicSharedMemorySize, G1_SMEM);
        cudaFuncSetAttribute(gemm1_phase_kernel<true>,
                             cudaFuncAttributeMaxDynamicSharedMemorySize, G1_SMEM);
        dim3 grid(H_SZ / G1_BN, BT / G1_BM);   // (16, 64)
        gemm1_phase_kernel<false><<<grid, 256, G1_SMEM>>>(x, W1, g_H_p, 0);
        gemm1_phase_kernel<true ><<<grid, 256, G1_SMEM>>>(x, W1, g_H_p, G1_KC);
    }

    // 2) sequential timesteps: one fused kernel per step
    for (int t = 0; t < T_STEPS; t++)
        step_kernel<<<B_SZ, 256>>>(t, out_ch, out_com);

    // 3) passthrough x
    cudaMemcpyAsync(out_x, x, (size_t)BT * F_IN * sizeof(float),
                    cudaMemcpyDeviceToDevice, 0);

    (void)in_sizes; (void)n_in; (void)out_size;
}

// round 15
// speedup vs baseline: 1.0787x; 1.0787x over previous
#include <cuda_runtime.h>
#include <cstddef>

// Problem constants (fixed shapes from reference setup_inputs)
#define T_STEPS 16
#define B_SZ    512
#define F_IN    2048
#define H_SZ    2048
#define OUT_SZ  1024
#define BT      (B_SZ * T_STEPS)   // 8192

// Scratch (device globals: allocation-free per harness rules)
// g_H is T-MAJOR: g_H[((t * B_SZ) + b) * H_SZ + h]
__device__ float g_H  [ (size_t)BT  * H_SZ   ];   // 64 MB
__device__ float g_v1 [ (size_t)B_SZ * H_SZ  ];   // membrane lif1
__device__ float g_v2 [ (size_t)B_SZ * OUT_SZ];   // membrane lif_out
__device__ float g_W2T[ (size_t)H_SZ * OUT_SZ];   // 8 MB: W2 transposed [H, OUT]

// ---------------------------------------------------------------------------
// init: zero membranes
// ---------------------------------------------------------------------------
__global__ void init_state_kernel() {
    size_t i = (size_t)blockIdx.x * blockDim.x + threadIdx.x;
    size_t n1 = (size_t)B_SZ * H_SZ;
    size_t n2 = (size_t)B_SZ * OUT_SZ;
    if (i < n1) g_v1[i] = 0.0f;
    if (i < n2) g_v2[i] = 0.0f;
}

// ---------------------------------------------------------------------------
// Transpose W2 [OUT, H] -> W2T [H, OUT].  32x32 smem tiles.
// ---------------------------------------------------------------------------
__global__ void transpose_w2_kernel(const float* __restrict__ W2)
{
    __shared__ float tile[32][33];
    int o0 = blockIdx.y * 32;
    int k0 = blockIdx.x * 32;
    int tx = threadIdx.x, ty = threadIdx.y;   // 32 x 8

    #pragma unroll
    for (int r = 0; r < 32; r += 8)
        tile[ty + r][tx] = W2[(size_t)(o0 + ty + r) * H_SZ + k0 + tx];
    __syncthreads();
    #pragma unroll
    for (int r = 0; r < 32; r += 8)
        g_W2T[(size_t)(k0 + ty + r) * OUT_SZ + o0 + tx] = tile[tx][ty + r];
}

// ---------------------------------------------------------------------------
// GEMM1 phase kernel — R13 version (BK=16, strided fragments, 2 CTAs/SM),
// with t-major output row mapping and an m_base for the t-split halves.
// ACCUMULATION CONTRACT (frozen, R6): per element, 2 contiguous K-chunks of
// 1024, each a serial ascending FMA chain from zero, merged sequentially.
//   Phase A (ACCUM=false): C = chain(K[0:1024])
//   Phase B (ACCUM=true):  C = __fadd_rn(C, chain(K[1024:2048]))
// Output row m (t-major: m = t*512 + b) reads x row (b*16 + t).
// Row permutation + M-partition only — per-element chain order unchanged.
// ---------------------------------------------------------------------------
#define G1_BM 128
#define G1_BN 128
#define G1_BK 16
#define G1_KC 1024
#define G1_NT (G1_KC / G1_BK)   // 64 tiles per phase

__device__ __forceinline__ int x_row_of(int m) {
    // m = t*512 + b  ->  x row = b*16 + t
    return ((m & (B_SZ - 1)) << 4) + (m >> 9);
}

template<bool ACCUM>
__global__ __launch_bounds__(256, 2)
void gemm1_phase_kernel(const float* __restrict__ A,    // x   [BT, F_IN] (b-major)
                        const float* __restrict__ Bm,   // W1  [H, F_IN]
                        float* __restrict__ C,          // g_H [BT, H] (t-major)
                        int k_base, int m_base)
{
    __shared__ float As[2][G1_BK][G1_BM];
    __shared__ float Bs[2][G1_BK][G1_BN];

    const int tid  = threadIdx.x;
    const int m0   = m_base + blockIdx.y * G1_BM;
    const int n0   = blockIdx.x * G1_BN;

    // Strided-fragment mapping: warp 8x4, CTA warps 2x4.
    const int lane = tid & 31;
    const int warp = tid >> 5;
    const int ly   = lane >> 2;          // 0..7
    const int lx   = lane & 3;           // 0..3
    const int wy   = warp >> 2;          // 0..1
    const int wx   = warp & 3;           // 0..3
    const int rr   = (wy * 8 + ly) * 4;  // row base
    const int cc   = (wx * 4 + lx) * 4;  // col base

    // Staging (global->smem) mapping.
    const int r0 = tid >> 2;
    const int c0 = tid & 3;
    const int r1 = (tid + 256) >> 2;
    const int c1 = (tid + 256) & 3;

    const float* Arow0 = A  + (size_t)x_row_of(m0 + r0) * F_IN + k_base + c0 * 4;
    const float* Arow1 = A  + (size_t)x_row_of(m0 + r1) * F_IN + k_base + c1 * 4;
    const float* Brow0 = Bm + (size_t)(n0 + r0) * F_IN + k_base + c0 * 4;
    const float* Brow1 = Bm + (size_t)(n0 + r1) * F_IN + k_base + c1 * 4;

    float acc[8][8];
    #pragma unroll
    for (int i = 0; i < 8; i++)
        #pragma unroll
        for (int j = 0; j < 8; j++)
            acc[i][j] = 0.0f;

    float4 ra0, ra1, rb0, rb1;

    // Prologue: tile 0 -> buffer 0
    ra0 = *reinterpret_cast<const float4*>(Arow0);
    ra1 = *reinterpret_cast<const float4*>(Arow1);
    rb0 = *reinterpret_cast<const float4*>(Brow0);
    rb1 = *reinterpret_cast<const float4*>(Brow1);
    As[0][c0*4+0][r0] = ra0.x; As[0][c0*4+1][r0] = ra0.y;
    As[0][c0*4+2][r0] = ra0.z; As[0][c0*4+3][r0] = ra0.w;
    As[0][c1*4+0][r1] = ra1.x; As[0][c1*4+1][r1] = ra1.y;
    As[0][c1*4+2][r1] = ra1.z; As[0][c1*4+3][r1] = ra1.w;
    Bs[0][c0*4+0][r0] = rb0.x; Bs[0][c0*4+1][r0] = rb0.y;
    Bs[0][c0*4+2][r0] = rb0.z; Bs[0][c0*4+3][r0] = rb0.w;
    Bs[0][c1*4+0][r1] = rb1.x; Bs[0][c1*4+1][r1] = rb1.y;
    Bs[0][c1*4+2][r1] = rb1.z; Bs[0][c1*4+3][r1] = rb1.w;
    __syncthreads();

    for (int kt = 0; kt < G1_NT; kt++) {
        const int buf = kt & 1;

        if (kt + 1 < G1_NT) {
            const int koff = (kt + 1) * G1_BK;
            ra0 = *reinterpret_cast<const float4*>(Arow0 + koff);
            ra1 = *reinterpret_cast<const float4*>(Arow1 + koff);
            rb0 = *reinterpret_cast<const float4*>(Brow0 + koff);
            rb1 = *reinterpret_cast<const float4*>(Brow1 + koff);
        }

        #pragma unroll
        for (int k = 0; k < G1_BK; k++) {
            float4 a_lo = *reinterpret_cast<const float4*>(&As[buf][k][rr]);
            float4 a_hi = *reinterpret_cast<const float4*>(&As[buf][k][rr + 64]);
            float4 b_lo = *reinterpret_cast<const float4*>(&Bs[buf][k][cc]);
            float4 b_hi = *reinterpret_cast<const float4*>(&Bs[buf][k][cc + 64]);
            float a[8] = {a_lo.x, a_lo.y, a_lo.z, a_lo.w,
                          a_hi.x, a_hi.y, a_hi.z, a_hi.w};
            float b[8] = {b_lo.x, b_lo.y, b_lo.z, b_lo.w,
                          b_hi.x, b_hi.y, b_hi.z, b_hi.w};
            #pragma unroll
            for (int i = 0; i < 8; i++)
                #pragma unroll
                for (int j = 0; j < 8; j++)
                    acc[i][j] = fmaf(a[i], b[j], acc[i][j]);
        }

        if (kt + 1 < G1_NT) {
            const int nb = 1 - buf;
            As[nb][c0*4+0][r0] = ra0.x; As[nb][c0*4+1][r0] = ra0.y;
            As[nb][c0*4+2][r0] = ra0.z; As[nb][c0*4+3][r0] = ra0.w;
            As[nb][c1*4+0][r1] = ra1.x; As[nb][c1*4+1][r1] = ra1.y;
            As[nb][c1*4+2][r1] = ra1.z; As[nb][c1*4+3][r1] = ra1.w;
            Bs[nb][c0*4+0][r0] = rb0.x; Bs[nb][c0*4+1][r0] = rb0.y;
            Bs[nb][c0*4+2][r0] = rb0.z; Bs[nb][c0*4+3][r0] = rb0.w;
            Bs[nb][c1*4+0][r1] = rb1.x; Bs[nb][c1*4+1][r1] = rb1.y;
            Bs[nb][c1*4+2][r1] = rb1.z; Bs[nb][c1*4+3][r1] = rb1.w;
        }
        __syncthreads();
    }

    // Epilogue: rows {rr+i, rr+64+i}, cols {cc..cc+3, cc+64..cc+67}
    #pragma unroll
    for (int i = 0; i < 8; i++) {
        const int row = m0 + ((i < 4) ? (rr + i) : (rr + 64 + i - 4));
        #pragma unroll
        for (int jh = 0; jh < 2; jh++) {
            const int col = n0 + cc + jh * 64;
            float* cp = C + (size_t)row * H_SZ + col;
            const int j0 = jh * 4;
            if (ACCUM) {
                float4 prev = *reinterpret_cast<const float4*>(cp);
                float4 v = make_float4(__fadd_rn(prev.x, acc[i][j0+0]),
                                       __fadd_rn(prev.y, acc[i][j0+1]),
                                       __fadd_rn(prev.z, acc[i][j0+2]),
                                       __fadd_rn(prev.w, acc[i][j0+3]));
                *reinterpret_cast<float4*>(cp) = v;
            } else {
                float4 v = make_float4(acc[i][j0+0], acc[i][j0+1],
                                       acc[i][j0+2], acc[i][j0+3]);
                *reinterpret_cast<float4*>(cp) = v;
            }
        }
    }
}

// ---------------------------------------------------------------------------
// Fused timestep kernel: LIF1 + ordered compaction (smem) + sparse GEMM2 +
// LIF2. One CTA (256 threads) per batch row b. Orders identical to R8-R13.
// Reads g_H in T-MAJOR layout; writes outputs in the required b-major layout.
// ---------------------------------------------------------------------------
__global__ __launch_bounds__(256)
void step_kernel(int t, float* __restrict__ out_ch, float* __restrict__ out_com)
{
    __shared__ int sk[H_SZ];    // spike k-indices, ascending (8 KB)
    __shared__ int sc[256];     // scan workspace

    const int b   = blockIdx.x;
    const int tid = threadIdx.x;
    const int PER = H_SZ / 256;   // 8

    const size_t hbase  = ((size_t)t * B_SZ + b) * H_SZ + (size_t)tid * PER; // t-major
    const size_t chbase = ((size_t)b * T_STEPS + t) * H_SZ + (size_t)tid * PER; // output
    const size_t vbase  = (size_t)b * H_SZ + (size_t)tid * PER;

    float h[PER], v[PER];
    #pragma unroll
    for (int j = 0; j < PER; j += 4) {
        float4 hv = *reinterpret_cast<const float4*>(&g_H[hbase + j]);
        h[j] = hv.x; h[j+1] = hv.y; h[j+2] = hv.z; h[j+3] = hv.w;
        float4 vv = *reinterpret_cast<const float4*>(&g_v1[vbase + j]);
        v[j] = vv.x; v[j+1] = vv.y; v[j+2] = vv.z; v[j+3] = vv.w;
    }

    float s[PER];
    int cnt = 0;
    #pragma unroll
    for (int j = 0; j < PER; j++) {
        float nv = __fmul_rn(__fadd_rn(v[j], h[j]), 0.5f);   // single rounding
        s[j] = (nv >= 0.5f) ? 1.0f : 0.0f;
        v[j] = (s[j] != 0.0f) ? 0.0f : nv;
        cnt += (s[j] != 0.0f) ? 1 : 0;
    }

    #pragma unroll
    for (int j = 0; j < PER; j += 4) {
        *reinterpret_cast<float4*>(&out_ch[chbase + j]) =
            make_float4(s[j], s[j+1], s[j+2], s[j+3]);
        *reinterpret_cast<float4*>(&g_v1[vbase + j]) =
            make_float4(v[j], v[j+1], v[j+2], v[j+3]);
    }

    // block inclusive scan of counts
    sc[tid] = cnt;
    __syncthreads();
    #pragma unroll
    for (int off = 1; off < 256; off <<= 1) {
        int add = (tid >= off) ? sc[tid - off] : 0;
        __syncthreads();
        sc[tid] += add;
        __syncthreads();
    }
    int pos = sc[tid] - cnt;   // exclusive prefix

    #pragma unroll
    for (int j = 0; j < PER; j++)
        if (s[j] != 0.0f)
            sk[pos++] = tid * PER + j;

    const int total = sc[255];
    __syncthreads();   // sk fully written before reads

    // sparse GEMM2: ascending-k sum == dense serial FMA chain (bitwise)
    const int o = tid * 4;
    float a0 = 0.0f, a1 = 0.0f, a2 = 0.0f, a3 = 0.0f;

    #pragma unroll 4
    for (int i = 0; i < total; i++) {
        const int k = sk[i];
        float4 w = *reinterpret_cast<const float4*>(&g_W2T[(size_t)k * OUT_SZ + o]);
        a0 = __fadd_rn(a0, w.x);
        a1 = __fadd_rn(a1, w.y);
        a2 = __fadd_rn(a2, w.z);
        a3 = __fadd_rn(a3, w.w);
    }

    // LIF2 epilogue
    const size_t v2base = (size_t)b * OUT_SZ + o;
    float4 vv = *reinterpret_cast<const float4*>(&g_v2[v2base]);
    float acc[4] = {a0, a1, a2, a3};
    float vin[4] = {vv.x, vv.y, vv.z, vv.w};
    float sp[4], vout[4];
    #pragma unroll
    for (int j = 0; j < 4; j++) {
        float nv = __fmul_rn(__fadd_rn(vin[j], acc[j]), 0.5f);
        sp[j]   = (nv >= 0.5f) ? 1.0f : 0.0f;
        vout[j] = (sp[j] != 0.0f) ? 0.0f : nv;
    }
    *reinterpret_cast<float4*>(
        &out_com[((size_t)b * T_STEPS + t) * OUT_SZ + o]) =
        make_float4(sp[0], sp[1], sp[2], sp[3]);
    *reinterpret_cast<float4*>(&g_v2[v2base]) =
        make_float4(vout[0], vout[1], vout[2], vout[3]);
}

// ---------------------------------------------------------------------------
// Static side-stream + events (created once; identical work every call;
// no device-memory allocation involved).
// ---------------------------------------------------------------------------
struct OverlapRes {
    cudaStream_t s2;
    cudaEvent_t  ev_fork, ev_join;
    OverlapRes() {
        cudaStreamCreateWithFlags(&s2, cudaStreamNonBlocking);
        cudaEventCreateWithFlags(&ev_fork, cudaEventDisableTiming);
        cudaEventCreateWithFlags(&ev_join, cudaEventDisableTiming);
    }
};
static OverlapRes g_ov;

// ---------------------------------------------------------------------------
// kernel_launch: graph-capturable, allocation-free.
// Inputs: d_in[0]=x [B,T,F_IN] f32, d_in[1]=W1 [H,F_IN] f32, d_in[2]=W2 [OUT,H] f32
// Output: concat(com_spk [B,T,OUT], ch_spk [B,T,H], x [B,T,F_IN]) f32
// ---------------------------------------------------------------------------
extern "C" void kernel_launch(void* const* d_in, const int* in_sizes, int n_in,
                              void* d_out, int out_size)
{
    const float* x  = (const float*)d_in[0];
    const float* W1 = (const float*)d_in[1];
    const float* W2 = (const float*)d_in[2];
    float* out = (float*)d_out;

    const size_t COM_OFF = 0;
    const size_t CH_OFF  = (size_t)BT * OUT_SZ;
    const size_t X_OFF   = CH_OFF + (size_t)BT * H_SZ;

    float* out_com = out + COM_OFF;
    float* out_ch  = out + CH_OFF;
    float* out_x   = out + X_OFF;

    float* g_H_p;
    cudaGetSymbolAddress((void**)&g_H_p, g_H);

    // ---- fork side stream (joins before return) ----
    cudaEventRecord(g_ov.ev_fork, 0);
    cudaStreamWaitEvent(g_ov.s2, g_ov.ev_fork, 0);

    // side stream: x passthrough + GEMM1 for t=8..15 (rows 4096..8191)
    {
        cudaMemcpyAsync(out_x, x, (size_t)BT * F_IN * sizeof(float),
                        cudaMemcpyDeviceToDevice, g_ov.s2);
        dim3 grid(H_SZ / G1_BN, (BT / 2) / G1_BM);   // (16, 32)
        gemm1_phase_kernel<false><<<grid, 256, 0, g_ov.s2>>>(x, W1, g_H_p, 0,      BT / 2);
        gemm1_phase_kernel<true ><<<grid, 256, 0, g_ov.s2>>>(x, W1, g_H_p, G1_KC,  BT / 2);
        cudaEventRecord(g_ov.ev_join, g_ov.s2);
    }

    // default stream: init + transpose + GEMM1 for t=0..7
    {
        size_t n = (size_t)B_SZ * H_SZ;
        init_state_kernel<<<(unsigned)((n + 255) / 256), 256>>>();
        dim3 tgrid(H_SZ / 32, OUT_SZ / 32);
        transpose_w2_kernel<<<tgrid, dim3(32, 8)>>>(W2);

        dim3 grid(H_SZ / G1_BN, (BT / 2) / G1_BM);   // (16, 32)
        gemm1_phase_kernel<false><<<grid, 256>>>(x, W1, g_H_p, 0,     0);
        gemm1_phase_kernel<true ><<<grid, 256>>>(x, W1, g_H_p, G1_KC, 0);
    }

    // steps 0..7 overlap with side-stream GEMM1
    for (int t = 0; t < T_STEPS / 2; t++)
        step_kernel<<<B_SZ, 256>>>(t, out_ch, out_com);

    // join side stream, then steps 8..15
    cudaStreamWaitEvent(0, g_ov.ev_join, 0);
    for (int t = T_STEPS / 2; t < T_STEPS; t++)
        step_kernel<<<B_SZ, 256>>>(t, out_ch, out_com);

    (void)in_sizes; (void)n_in; (void)out_size;
}

// round 16
// speedup vs baseline: 1.1035x; 1.0230x over previous
#include <cuda_runtime.h>
#include <cstddef>

// Problem constants (fixed shapes from reference setup_inputs)
#define T_STEPS 16
#define B_SZ    512
#define F_IN    2048
#define H_SZ    2048
#define OUT_SZ  1024
#define BT      (B_SZ * T_STEPS)   // 8192

// Pipeline grouping: 4 groups x 4 timesteps
#define N_GROUPS 4
#define T_PER_G  (T_STEPS / N_GROUPS)          // 4
#define ROWS_PER_G (T_PER_G * B_SZ)            // 2048

// Scratch (device globals: allocation-free per harness rules)
// g_H is T-MAJOR: g_H[((t * B_SZ) + b) * H_SZ + h]
__device__ float g_H  [ (size_t)BT  * H_SZ   ];   // 64 MB
__device__ float g_v1 [ (size_t)B_SZ * H_SZ  ];   // membrane lif1
__device__ float g_v2 [ (size_t)B_SZ * OUT_SZ];   // membrane lif_out
__device__ float g_W2T[ (size_t)H_SZ * OUT_SZ];   // 8 MB: W2 transposed [H, OUT]

// ---------------------------------------------------------------------------
// init: zero membranes
// ---------------------------------------------------------------------------
__global__ void init_state_kernel() {
    size_t i = (size_t)blockIdx.x * blockDim.x + threadIdx.x;
    size_t n1 = (size_t)B_SZ * H_SZ;
    size_t n2 = (size_t)B_SZ * OUT_SZ;
    if (i < n1) g_v1[i] = 0.0f;
    if (i < n2) g_v2[i] = 0.0f;
}

// ---------------------------------------------------------------------------
// Transpose W2 [OUT, H] -> W2T [H, OUT].  32x32 smem tiles.
// ---------------------------------------------------------------------------
__global__ void transpose_w2_kernel(const float* __restrict__ W2)
{
    __shared__ float tile[32][33];
    int o0 = blockIdx.y * 32;
    int k0 = blockIdx.x * 32;
    int tx = threadIdx.x, ty = threadIdx.y;   // 32 x 8

    #pragma unroll
    for (int r = 0; r < 32; r += 8)
        tile[ty + r][tx] = W2[(size_t)(o0 + ty + r) * H_SZ + k0 + tx];
    __syncthreads();
    #pragma unroll
    for (int r = 0; r < 32; r += 8)
        g_W2T[(size_t)(k0 + ty + r) * OUT_SZ + o0 + tx] = tile[tx][ty + r];
}

// ---------------------------------------------------------------------------
// GEMM1 phase kernel — R13 config (BK=16, strided fragments, 2 CTAs/SM),
// t-major output rows, m_base selects the t-group slice.
// ACCUMULATION CONTRACT (frozen, R6): per element, 2 contiguous K-chunks of
// 1024, each a serial ascending FMA chain from zero, merged sequentially.
//   Phase A (ACCUM=false): C = chain(K[0:1024])
//   Phase B (ACCUM=true):  C = __fadd_rn(C, chain(K[1024:2048]))
// Output row m (t-major: m = t*512 + b) reads x row (b*16 + t).
// ---------------------------------------------------------------------------
#define G1_BM 128
#define G1_BN 128
#define G1_BK 16
#define G1_KC 1024
#define G1_NT (G1_KC / G1_BK)   // 64 tiles per phase

__device__ __forceinline__ int x_row_of(int m) {
    // m = t*512 + b  ->  x row = b*16 + t
    return ((m & (B_SZ - 1)) << 4) + (m >> 9);
}

template<bool ACCUM>
__global__ __launch_bounds__(256, 2)
void gemm1_phase_kernel(const float* __restrict__ A,    // x   [BT, F_IN] (b-major)
                        const float* __restrict__ Bm,   // W1  [H, F_IN]
                        float* __restrict__ C,          // g_H [BT, H] (t-major)
                        int k_base, int m_base)
{
    __shared__ float As[2][G1_BK][G1_BM];
    __shared__ float Bs[2][G1_BK][G1_BN];

    const int tid  = threadIdx.x;
    const int m0   = m_base + blockIdx.y * G1_BM;
    const int n0   = blockIdx.x * G1_BN;

    // Strided-fragment mapping: warp 8x4, CTA warps 2x4.
    const int lane = tid & 31;
    const int warp = tid >> 5;
    const int ly   = lane >> 2;          // 0..7
    const int lx   = lane & 3;           // 0..3
    const int wy   = warp >> 2;          // 0..1
    const int wx   = warp & 3;           // 0..3
    const int rr   = (wy * 8 + ly) * 4;  // row base
    const int cc   = (wx * 4 + lx) * 4;  // col base

    // Staging (global->smem) mapping.
    const int r0 = tid >> 2;
    const int c0 = tid & 3;
    const int r1 = (tid + 256) >> 2;
    const int c1 = (tid + 256) & 3;

    const float* Arow0 = A  + (size_t)x_row_of(m0 + r0) * F_IN + k_base + c0 * 4;
    const float* Arow1 = A  + (size_t)x_row_of(m0 + r1) * F_IN + k_base + c1 * 4;
    const float* Brow0 = Bm + (size_t)(n0 + r0) * F_IN + k_base + c0 * 4;
    const float* Brow1 = Bm + (size_t)(n0 + r1) * F_IN + k_base + c1 * 4;

    float acc[8][8];
    #pragma unroll
    for (int i = 0; i < 8; i++)
        #pragma unroll
        for (int j = 0; j < 8; j++)
            acc[i][j] = 0.0f;

    float4 ra0, ra1, rb0, rb1;

    // Prologue: tile 0 -> buffer 0
    ra0 = *reinterpret_cast<const float4*>(Arow0);
    ra1 = *reinterpret_cast<const float4*>(Arow1);
    rb0 = *reinterpret_cast<const float4*>(Brow0);
    rb1 = *reinterpret_cast<const float4*>(Brow1);
    As[0][c0*4+0][r0] = ra0.x; As[0][c0*4+1][r0] = ra0.y;
    As[0][c0*4+2][r0] = ra0.z; As[0][c0*4+3][r0] = ra0.w;
    As[0][c1*4+0][r1] = ra1.x; As[0][c1*4+1][r1] = ra1.y;
    As[0][c1*4+2][r1] = ra1.z; As[0][c1*4+3][r1] = ra1.w;
    Bs[0][c0*4+0][r0] = rb0.x; Bs[0][c0*4+1][r0] = rb0.y;
    Bs[0][c0*4+2][r0] = rb0.z; Bs[0][c0*4+3][r0] = rb0.w;
    Bs[0][c1*4+0][r1] = rb1.x; Bs[0][c1*4+1][r1] = rb1.y;
    Bs[0][c1*4+2][r1] = rb1.z; Bs[0][c1*4+3][r1] = rb1.w;
    __syncthreads();

    for (int kt = 0; kt < G1_NT; kt++) {
        const int buf = kt & 1;

        if (kt + 1 < G1_NT) {
            const int koff = (kt + 1) * G1_BK;
            ra0 = *reinterpret_cast<const float4*>(Arow0 + koff);
            ra1 = *reinterpret_cast<const float4*>(Arow1 + koff);
            rb0 = *reinterpret_cast<const float4*>(Brow0 + koff);
            rb1 = *reinterpret_cast<const float4*>(Brow1 + koff);
        }

        #pragma unroll
        for (int k = 0; k < G1_BK; k++) {
            float4 a_lo = *reinterpret_cast<const float4*>(&As[buf][k][rr]);
            float4 a_hi = *reinterpret_cast<const float4*>(&As[buf][k][rr + 64]);
            float4 b_lo = *reinterpret_cast<const float4*>(&Bs[buf][k][cc]);
            float4 b_hi = *reinterpret_cast<const float4*>(&Bs[buf][k][cc + 64]);
            float a[8] = {a_lo.x, a_lo.y, a_lo.z, a_lo.w,
                          a_hi.x, a_hi.y, a_hi.z, a_hi.w};
            float b[8] = {b_lo.x, b_lo.y, b_lo.z, b_lo.w,
                          b_hi.x, b_hi.y, b_hi.z, b_hi.w};
            #pragma unroll
            for (int i = 0; i < 8; i++)
                #pragma unroll
                for (int j = 0; j < 8; j++)
                    acc[i][j] = fmaf(a[i], b[j], acc[i][j]);
        }

        if (kt + 1 < G1_NT) {
            const int nb = 1 - buf;
            As[nb][c0*4+0][r0] = ra0.x; As[nb][c0*4+1][r0] = ra0.y;
            As[nb][c0*4+2][r0] = ra0.z; As[nb][c0*4+3][r0] = ra0.w;
            As[nb][c1*4+0][r1] = ra1.x; As[nb][c1*4+1][r1] = ra1.y;
            As[nb][c1*4+2][r1] = ra1.z; As[nb][c1*4+3][r1] = ra1.w;
            Bs[nb][c0*4+0][r0] = rb0.x; Bs[nb][c0*4+1][r0] = rb0.y;
            Bs[nb][c0*4+2][r0] = rb0.z; Bs[nb][c0*4+3][r0] = rb0.w;
            Bs[nb][c1*4+0][r1] = rb1.x; Bs[nb][c1*4+1][r1] = rb1.y;
            Bs[nb][c1*4+2][r1] = rb1.z; Bs[nb][c1*4+3][r1] = rb1.w;
        }
        __syncthreads();
    }

    // Epilogue: rows {rr+i, rr+64+i}, cols {cc..cc+3, cc+64..cc+67}
    #pragma unroll
    for (int i = 0; i < 8; i++) {
        const int row = m0 + ((i < 4) ? (rr + i) : (rr + 64 + i - 4));
        #pragma unroll
        for (int jh = 0; jh < 2; jh++) {
            const int col = n0 + cc + jh * 64;
            float* cp = C + (size_t)row * H_SZ + col;
            const int j0 = jh * 4;
            if (ACCUM) {
                float4 prev = *reinterpret_cast<const float4*>(cp);
                float4 v = make_float4(__fadd_rn(prev.x, acc[i][j0+0]),
                                       __fadd_rn(prev.y, acc[i][j0+1]),
                                       __fadd_rn(prev.z, acc[i][j0+2]),
                                       __fadd_rn(prev.w, acc[i][j0+3]));
                *reinterpret_cast<float4*>(cp) = v;
            } else {
                float4 v = make_float4(acc[i][j0+0], acc[i][j0+1],
                                       acc[i][j0+2], acc[i][j0+3]);
                *reinterpret_cast<float4*>(cp) = v;
            }
        }
    }
}

// ---------------------------------------------------------------------------
// Fused timestep kernel: LIF1 + ordered compaction (smem) + sparse GEMM2 +
// LIF2. One CTA (256 threads) per batch row b. Orders identical to R8-R15.
// Reads g_H in T-MAJOR layout; writes outputs in b-major layout.
// ---------------------------------------------------------------------------
__global__ __launch_bounds__(256)
void step_kernel(int t, float* __restrict__ out_ch, float* __restrict__ out_com)
{
    __shared__ int sk[H_SZ];    // spike k-indices, ascending (8 KB)
    __shared__ int sc[256];     // scan workspace

    const int b   = blockIdx.x;
    const int tid = threadIdx.x;
    const int PER = H_SZ / 256;   // 8

    const size_t hbase  = ((size_t)t * B_SZ + b) * H_SZ + (size_t)tid * PER; // t-major
    const size_t chbase = ((size_t)b * T_STEPS + t) * H_SZ + (size_t)tid * PER;
    const size_t vbase  = (size_t)b * H_SZ + (size_t)tid * PER;

    float h[PER], v[PER];
    #pragma unroll
    for (int j = 0; j < PER; j += 4) {
        float4 hv = *reinterpret_cast<const float4*>(&g_H[hbase + j]);
        h[j] = hv.x; h[j+1] = hv.y; h[j+2] = hv.z; h[j+3] = hv.w;
        float4 vv = *reinterpret_cast<const float4*>(&g_v1[vbase + j]);
        v[j] = vv.x; v[j+1] = vv.y; v[j+2] = vv.z; v[j+3] = vv.w;
    }

    float s[PER];
    int cnt = 0;
    #pragma unroll
    for (int j = 0; j < PER; j++) {
        float nv = __fmul_rn(__fadd_rn(v[j], h[j]), 0.5f);   // single rounding
        s[j] = (nv >= 0.5f) ? 1.0f : 0.0f;
        v[j] = (s[j] != 0.0f) ? 0.0f : nv;
        cnt += (s[j] != 0.0f) ? 1 : 0;
    }

    #pragma unroll
    for (int j = 0; j < PER; j += 4) {
        *reinterpret_cast<float4*>(&out_ch[chbase + j]) =
            make_float4(s[j], s[j+1], s[j+2], s[j+3]);
        *reinterpret_cast<float4*>(&g_v1[vbase + j]) =
            make_float4(v[j], v[j+1], v[j+2], v[j+3]);
    }

    // block inclusive scan of counts
    sc[tid] = cnt;
    __syncthreads();
    #pragma unroll
    for (int off = 1; off < 256; off <<= 1) {
        int add = (tid >= off) ? sc[tid - off] : 0;
        __syncthreads();
        sc[tid] += add;
        __syncthreads();
    }
    int pos = sc[tid] - cnt;   // exclusive prefix

    #pragma unroll
    for (int j = 0; j < PER; j++)
        if (s[j] != 0.0f)
            sk[pos++] = tid * PER + j;

    const int total = sc[255];
    __syncthreads();   // sk fully written before reads

    // sparse GEMM2: ascending-k sum == dense serial FMA chain (bitwise)
    const int o = tid * 4;
    float a0 = 0.0f, a1 = 0.0f, a2 = 0.0f, a3 = 0.0f;

    #pragma unroll 4
    for (int i = 0; i < total; i++) {
        const int k = sk[i];
        float4 w = *reinterpret_cast<const float4*>(&g_W2T[(size_t)k * OUT_SZ + o]);
        a0 = __fadd_rn(a0, w.x);
        a1 = __fadd_rn(a1, w.y);
        a2 = __fadd_rn(a2, w.z);
        a3 = __fadd_rn(a3, w.w);
    }

    // LIF2 epilogue
    const size_t v2base = (size_t)b * OUT_SZ + o;
    float4 vv = *reinterpret_cast<const float4*>(&g_v2[v2base]);
    float acc[4] = {a0, a1, a2, a3};
    float vin[4] = {vv.x, vv.y, vv.z, vv.w};
    float sp[4], vout[4];
    #pragma unroll
    for (int j = 0; j < 4; j++) {
        float nv = __fmul_rn(__fadd_rn(vin[j], acc[j]), 0.5f);
        sp[j]   = (nv >= 0.5f) ? 1.0f : 0.0f;
        vout[j] = (sp[j] != 0.0f) ? 0.0f : nv;
    }
    *reinterpret_cast<float4*>(
        &out_com[((size_t)b * T_STEPS + t) * OUT_SZ + o]) =
        make_float4(sp[0], sp[1], sp[2], sp[3]);
    *reinterpret_cast<float4*>(&g_v2[v2base]) =
        make_float4(vout[0], vout[1], vout[2], vout[3]);
}

// ---------------------------------------------------------------------------
// Static streams + events (created once; identical graph every call;
// no device-memory allocation involved).
// ---------------------------------------------------------------------------
struct PipeRes {
    cudaStream_t sA, sB;
    cudaEvent_t  ev_fork;
    cudaEvent_t  eA[N_GROUPS], eB[N_GROUPS];
    PipeRes() {
        cudaStreamCreateWithFlags(&sA, cudaStreamNonBlocking);
        cudaStreamCreateWithFlags(&sB, cudaStreamNonBlocking);
        cudaEventCreateWithFlags(&ev_fork, cudaEventDisableTiming);
        for (int g = 0; g < N_GROUPS; g++) {
            cudaEventCreateWithFlags(&eA[g], cudaEventDisableTiming);
            cudaEventCreateWithFlags(&eB[g], cudaEventDisableTiming);
        }
    }
};
static PipeRes g_pr;

// ---------------------------------------------------------------------------
// kernel_launch: graph-capturable, allocation-free.
// Inputs: d_in[0]=x [B,T,F_IN] f32, d_in[1]=W1 [H,F_IN] f32, d_in[2]=W2 [OUT,H] f32
// Output: concat(com_spk [B,T,OUT], ch_spk [B,T,H], x [B,T,F_IN]) f32
// Pipeline: sA = phaseA groups; sB = memcpy + phaseB groups (after eA[g]);
// default = init/transpose + steps per group (after eB[g]).
// ---------------------------------------------------------------------------
extern "C" void kernel_launch(void* const* d_in, const int* in_sizes, int n_in,
                              void* d_out, int out_size)
{
    const float* x  = (const float*)d_in[0];
    const float* W1 = (const float*)d_in[1];
    const float* W2 = (const float*)d_in[2];
    float* out = (float*)d_out;

    const size_t COM_OFF = 0;
    const size_t CH_OFF  = (size_t)BT * OUT_SZ;
    const size_t X_OFF   = CH_OFF + (size_t)BT * H_SZ;

    float* out_com = out + COM_OFF;
    float* out_ch  = out + CH_OFF;
    float* out_x   = out + X_OFF;

    float* g_H_p;
    cudaGetSymbolAddress((void**)&g_H_p, g_H);

    // ---- fork both side streams from origin ----
    cudaEventRecord(g_pr.ev_fork, 0);
    cudaStreamWaitEvent(g_pr.sA, g_pr.ev_fork, 0);
    cudaStreamWaitEvent(g_pr.sB, g_pr.ev_fork, 0);

    // stream A: phase A per t-group, eager
    {
        dim3 grid(H_SZ / G1_BN, ROWS_PER_G / G1_BM);   // (16, 16) = 256 CTAs
        for (int g = 0; g < N_GROUPS; g++) {
            gemm1_phase_kernel<false><<<grid, 256, 0, g_pr.sA>>>(
                x, W1, g_H_p, 0, g * ROWS_PER_G);
            cudaEventRecord(g_pr.eA[g], g_pr.sA);
        }
    }

    // stream B: x passthrough (fills the A0 window), then phase B per group
    {
        cudaMemcpyAsync(out_x, x, (size_t)BT * F_IN * sizeof(float),
                        cudaMemcpyDeviceToDevice, g_pr.sB);
        dim3 grid(H_SZ / G1_BN, ROWS_PER_G / G1_BM);
        for (int g = 0; g < N_GROUPS; g++) {
            cudaStreamWaitEvent(g_pr.sB, g_pr.eA[g], 0);
            gemm1_phase_kernel<true><<<grid, 256, 0, g_pr.sB>>>(
                x, W1, g_H_p, G1_KC, g * ROWS_PER_G);
            cudaEventRecord(g_pr.eB[g], g_pr.sB);
        }
    }

    // default: init + transpose, then steps as groups complete
    {
        size_t n = (size_t)B_SZ * H_SZ;
        init_state_kernel<<<(unsigned)((n + 255) / 256), 256>>>();
        dim3 tgrid(H_SZ / 32, OUT_SZ / 32);
        transpose_w2_kernel<<<tgrid, dim3(32, 8)>>>(W2);
    }
    for (int g = 0; g < N_GROUPS; g++) {
        cudaStreamWaitEvent(0, g_pr.eB[g], 0);
        for (int t = g * T_PER_G; t < (g + 1) * T_PER_G; t++)
            step_kernel<<<B_SZ, 256>>>(t, out_ch, out_com);
    }

    // join stream A (B already joined via eB[last] -> default)
    cudaStreamWaitEvent(0, g_pr.eA[N_GROUPS - 1], 0);

    (void)in_sizes; (void)n_in; (void)out_size;
}